// round 1
// baseline (speedup 1.0000x reference)
#include <cuda_runtime.h>

#define NQ   13
#define DIM  8192
#define T1   1024      // threads for ansatz kernel
#define RPT  8         // amplitudes (complex) per thread: DIM / T1

#define K2_THREADS   256
#define ROWS_PER_BLK 32
#define COLS_PER_GRP 1024
#define NCOL_GRPS    (DIM / COLS_PER_GRP)            // 8
#define NROW_CHUNKS  (DIM / ROWS_PER_BLK)            // 256
#define NBLK2        (NCOL_GRPS * NROW_CHUNKS)       // 2048

// ---------------- device globals (no allocations allowed) ----------------
__device__ __align__(16) float g_psi_re[DIM];
__device__ __align__(16) float g_psi_im[DIM];
__device__ float g_z;                 // sum |psi_x|^2 * (13 - 2*popc(x))
__device__ float g_partials[NBLK2];

// =========================================================================
// Ansatz kernel: single block, state register-resident.
//   index x = (tid << 3) | r ;  bit tb of x:
//     tb in 0..2  -> register index bit   (register-local butterfly)
//     tb in 3..7  -> lane bit tb-3        (__shfl_xor butterfly)
//     tb in 8..12 -> warp-id bit          (shared-memory butterfly)
//   Rx butterfly: new = c*mine - i*s*partner   (symmetric on both sides)
//   CRX(control bit cb > target bit tb): apply butterfly only where bit cb == 1
// =========================================================================

template<int TB>
__device__ __forceinline__ void gate_local(float* ar, float* ai,
                                           float c, float s, int cb, int tid)
{
    // control: cb==-1 none; cb in 0..2 -> register-bit mask; cb>=3 -> thread bit
    bool tpred = (cb < 3) || ((tid >> (cb - 3)) & 1);
    if (!tpred) return;
    int cmask = (cb >= 0 && cb < 3) ? (1 << cb) : 0;
#pragma unroll
    for (int r = 0; r < RPT; r++) {
        if (r & (1 << TB)) continue;               // low side of pair only
        const int pr = r | (1 << TB);
        if ((r & cmask) == cmask) {                // control satisfied
            float a0r = ar[r],  a0i = ai[r];
            float a1r = ar[pr], a1i = ai[pr];
            ar[r]  = c * a0r + s * a1i;
            ai[r]  = c * a0i - s * a1r;
            ar[pr] = c * a1r + s * a0i;
            ai[pr] = c * a1i - s * a0r;
        }
    }
}

__device__ __forceinline__ void gate_shfl(float* ar, float* ai,
                                          float c, float s, int cb, int tb, int tid)
{
    bool pred = (cb < 0) || ((tid >> (cb - 3)) & 1);
    // cb >= 8 -> predicate is warp-uniform: whole warp may skip (shuffles intra-warp)
    if (cb >= 8 && !pred) return;
    const unsigned lm = 1u << (tb - 3);
#pragma unroll
    for (int r = 0; r < RPT; r++) {
        float br = __shfl_xor_sync(0xffffffffu, ar[r], lm);
        float bi = __shfl_xor_sync(0xffffffffu, ai[r], lm);
        if (pred) {
            float nr = c * ar[r] + s * bi;
            float ni = c * ai[r] - s * br;
            ar[r] = nr; ai[r] = ni;
        }
    }
}

__device__ __forceinline__ void gate_shared(float2* sh, float* ar, float* ai,
                                            float c, float s, int cb, int tb, int tid)
{
    const int base = tid * RPT;
#pragma unroll
    for (int r = 0; r < RPT; r++) sh[base + r] = make_float2(ar[r], ai[r]);
    __syncthreads();
    bool pred = (cb < 0) || ((tid >> (cb - 3)) & 1);
    if (pred) {
        const int pb = 1 << tb;
#pragma unroll
        for (int r = 0; r < RPT; r++) {
            float2 b = sh[(base + r) ^ pb];
            float nr = c * ar[r] + s * b.y;
            float ni = c * ai[r] - s * b.x;
            ar[r] = nr; ai[r] = ni;
        }
    }
    __syncthreads();
}

__device__ __forceinline__ void apply_gate(float2* sh, float* ar, float* ai,
                                           float c, float s, int cb, int tb, int tid)
{
    if (tb >= 8)      gate_shared(sh, ar, ai, c, s, cb, tb, tid);
    else if (tb >= 3) gate_shfl(ar, ai, c, s, cb, tb, tid);
    else if (tb == 2) gate_local<2>(ar, ai, c, s, cb, tid);
    else if (tb == 1) gate_local<1>(ar, ai, c, s, cb, tid);
    else              gate_local<0>(ar, ai, c, s, cb, tid);
}

__global__ void __launch_bounds__(T1)
ansatz_kernel(const float* __restrict__ theta,
              const float* __restrict__ phi,
              const float* __restrict__ alpha)
{
    extern __shared__ float2 sh[];   // DIM float2 = 64 KB exchange buffer
    const int tid = threadIdx.x;

    float ar[RPT], ai[RPT];
#pragma unroll
    for (int r = 0; r < RPT; r++) { ar[r] = 0.f; ai[r] = 0.f; }
    if (tid == 0) ar[0] = 1.f;       // |0...0>

    for (int l = 0; l < 2; l++) {
        float th = 0.5f * theta[l];
        float ph = 0.5f * phi[l];
        float al = 0.5f * alpha[l];
        float ct, st, ca, sa;
        sincosf(th, &st, &ct);
        sincosf(al, &sa, &ca);

        // Rx on every qubit (all commute; any order)
        for (int tb = 0; tb < NQ; tb++)
            apply_gate(sh, ar, ai, ct, st, -1, tb, tid);

        // Rz on every qubit == diagonal phase exp(i * ph * (2*popc(x) - 13))
#pragma unroll
        for (int r = 0; r < RPT; r++) {
            int x = (tid << 3) | r;
            float ang = ph * (float)(2 * __popc(x) - NQ);
            float sn, cs;
            sincosf(ang, &sn, &cs);
            float nr = ar[r] * cs - ai[r] * sn;
            float ni = ar[r] * sn + ai[r] * cs;
            ar[r] = nr; ai[r] = ni;
        }

        // CRX swap-network + undo-swap-network  ==  CRX(q_a -> q_b) for all a<b,
        // controls ascending (net permutation = identity).
        // qubit q <-> bit (NQ-1-q)
        for (int a = 0; a < NQ - 1; a++) {
            const int cb = (NQ - 1) - a;
            for (int b = a + 1; b < NQ; b++) {
                const int tb = (NQ - 1) - b;
                apply_gate(sh, ar, ai, ca, sa, cb, tb, tid);
            }
        }
    }

    // write psi (deinterleaved) + Z expectation term
    float z = 0.f;
#pragma unroll
    for (int r = 0; r < RPT; r++) {
        int x = (tid << 3) | r;
        g_psi_re[x] = ar[r];
        g_psi_im[x] = ai[r];
        z += (ar[r] * ar[r] + ai[r] * ai[r]) * (float)(NQ - 2 * __popc(x));
    }

    __syncthreads();                         // all shared reads done; reuse buffer
    float* zs = (float*)sh;
#pragma unroll
    for (int o = 16; o > 0; o >>= 1) z += __shfl_xor_sync(0xffffffffu, z, o);
    if ((tid & 31) == 0) zs[tid >> 5] = z;
    __syncthreads();
    if (tid < 32) {
        float v = zs[tid];                   // 32 warps
#pragma unroll
        for (int o = 16; o > 0; o >>= 1) v += __shfl_xor_sync(0xffffffffu, v, o);
        if (tid == 0) g_z = v;
    }
}

// =========================================================================
// Bilinear kernel: partial sums of Re( conj(psi_r) * H_rc * psi_c )
// per row:  d_r += H_rc * psi_c  (4 FMA/elem), then acc += Re(conj(psi_r)*d_r)
// =========================================================================
__global__ void __launch_bounds__(K2_THREADS)
bilinear_kernel(const float* __restrict__ Hr, const float* __restrict__ Hi)
{
    __shared__ float srr[ROWS_PER_BLK], sri[ROWS_PER_BLK];
    __shared__ float wsum[K2_THREADS / 32];

    const int t  = threadIdx.x;
    const int cg = blockIdx.x & (NCOL_GRPS - 1);
    const int rc = blockIdx.x >> 3;
    const int c0 = cg * COLS_PER_GRP + t * 4;
    const int r0 = rc * ROWS_PER_BLK;

    if (t < ROWS_PER_BLK) {
        srr[t] = g_psi_re[r0 + t];
        sri[t] = g_psi_im[r0 + t];
    }
    const float4 pcr = *(const float4*)(g_psi_re + c0);
    const float4 pci = *(const float4*)(g_psi_im + c0);
    __syncthreads();

    float acc = 0.f;
#pragma unroll 4
    for (int i = 0; i < ROWS_PER_BLK; i++) {
        const size_t off = (size_t)(r0 + i) * DIM + c0;
        const float4 hr = *(const float4*)(Hr + off);
        const float4 hi = *(const float4*)(Hi + off);
        const float prr = srr[i], pri = sri[i];

        float drr = 0.f, dri = 0.f;
        drr = fmaf(hr.x, pcr.x, drr); drr = fmaf(-hi.x, pci.x, drr);
        dri = fmaf(hr.x, pci.x, dri); dri = fmaf( hi.x, pcr.x, dri);
        drr = fmaf(hr.y, pcr.y, drr); drr = fmaf(-hi.y, pci.y, drr);
        dri = fmaf(hr.y, pci.y, dri); dri = fmaf( hi.y, pcr.y, dri);
        drr = fmaf(hr.z, pcr.z, drr); drr = fmaf(-hi.z, pci.z, drr);
        dri = fmaf(hr.z, pci.z, dri); dri = fmaf( hi.z, pcr.z, dri);
        drr = fmaf(hr.w, pcr.w, drr); drr = fmaf(-hi.w, pci.w, drr);
        dri = fmaf(hr.w, pci.w, dri); dri = fmaf( hi.w, pcr.w, dri);

        acc = fmaf(prr, drr, acc);
        acc = fmaf(pri, dri, acc);
    }

#pragma unroll
    for (int o = 16; o > 0; o >>= 1) acc += __shfl_xor_sync(0xffffffffu, acc, o);
    if ((t & 31) == 0) wsum[t >> 5] = acc;
    __syncthreads();
    if (t == 0) {
        float s = 0.f;
#pragma unroll
        for (int w = 0; w < K2_THREADS / 32; w++) s += wsum[w];
        g_partials[blockIdx.x] = s;
    }
}

// =========================================================================
// Final deterministic reduction + Z term -> d_out
// =========================================================================
__global__ void __launch_bounds__(256)
reduce_kernel(float* __restrict__ out, int out_size)
{
    __shared__ double wsumd[8];
    __shared__ float  res;
    const int t = threadIdx.x;

    double s = 0.0;
    for (int i = t; i < NBLK2; i += 256) s += (double)g_partials[i];
#pragma unroll
    for (int o = 16; o > 0; o >>= 1) s += __shfl_xor_sync(0xffffffffu, s, o);
    if ((t & 31) == 0) wsumd[t >> 5] = s;
    __syncthreads();
    if (t == 0) {
        double tot = 0.0;
#pragma unroll
        for (int w = 0; w < 8; w++) tot += wsumd[w];
        res = (float)(tot - 0.1 * (double)g_z);
    }
    __syncthreads();
    for (int i = t; i < out_size; i += 256) out[i] = res;
}

// =========================================================================
extern "C" void kernel_launch(void* const* d_in, const int* in_sizes, int n_in,
                              void* d_out, int out_size)
{
    const float* theta = (const float*)d_in[0];
    const float* phi   = (const float*)d_in[1];
    const float* alpha = (const float*)d_in[2];
    const float* Hr    = (const float*)d_in[3];
    const float* Hi    = (const float*)d_in[4];

    cudaFuncSetAttribute((const void*)ansatz_kernel,
                         cudaFuncAttributeMaxDynamicSharedMemorySize,
                         DIM * sizeof(float2));

    ansatz_kernel<<<1, T1, DIM * sizeof(float2)>>>(theta, phi, alpha);
    bilinear_kernel<<<NBLK2, K2_THREADS>>>(Hr, Hi);
    reduce_kernel<<<1, 256>>>((float*)d_out, out_size);
}

// round 6
// speedup vs baseline: 1.6686x; 1.6686x over previous
#include <cuda_runtime.h>

#define NQ   13
#define DIM  8192
#define T1   1024      // threads for ansatz kernel
#define RPT  8         // amplitudes (complex) per thread: DIM / T1
#define LAYERS 2

#define K2_THREADS   256
#define ROWS_PER_BLK 32
#define COLS_PER_GRP 1024
#define NCOL_GRPS    (DIM / COLS_PER_GRP)            // 8
#define NROW_CHUNKS  (DIM / ROWS_PER_BLK)            // 256
#define NBLK2        (NCOL_GRPS * NROW_CHUNKS)       // 2048

// ---------------- device globals (no allocations allowed) ----------------
__device__ __align__(16) float g_psi_re[DIM];
__device__ __align__(16) float g_psi_im[DIM];
__device__ float g_z;
__device__ float g_partials[NBLK2];

// =========================================================================
// Ansatz in the X basis (conjugated by H^N):
//   logical index x, bits: 0..2 = register, 3..7 = lane, 8..12 = warp.
//   Rx^N  -> diagonal phase exp(i*th*(2*popc(x)-13)),  th = theta/2
//   Rz^N  -> Rx(phi)-form butterfly on every bit
//   CRX fan (control bit c, targets all t<c) -> ONE butterfly on bit c:
//       new(x) = 0.5*[(a+b) + D*(a-b)],  D = exp(-i*ah*m),
//       m = c - 2*popc(x & (2^c-1)),  ah = alpha/2
//   init = all-ones (H^N|0> unnorm); final H^N butterflies; scale 1/8192.
//
// High-bit gates (8..12) run in a TRANSPOSED domain: a single XOR-swizzled
// shared exchange swaps the warp-bit group with the lane-bit group, so those
// gates become __shfl_xor butterflies. 5 shared roundtrips total.
// =========================================================================

// ---- transpose warp-bits <-> lane-bits (involution, conflict-free) ----
__device__ __forceinline__ void transpose_wl(float2* sh, float* ar, float* ai,
                                             int w, int lane)
{
#pragma unroll
    for (int r = 0; r < RPT; r++)
        sh[r * T1 + (w << 5) + (lane ^ w)] = make_float2(ar[r], ai[r]);
    __syncthreads();
#pragma unroll
    for (int r = 0; r < RPT; r++) {
        float2 b = sh[r * T1 + (lane << 5) + (w ^ lane)];
        ar[r] = b.x; ai[r] = b.y;
    }
    __syncthreads();
}

// ---- Rz-form butterfly (psi' = c*psi - i*s*psi_partner) ----
template<int TB>
__device__ __forceinline__ void rz_local(float* ar, float* ai, float c, float s)
{
#pragma unroll
    for (int r = 0; r < RPT; r++) {
        if (r & (1 << TB)) continue;
        const int pr = r | (1 << TB);
        float a0r = ar[r],  a0i = ai[r];
        float a1r = ar[pr], a1i = ai[pr];
        ar[r]  = c * a0r + s * a1i;
        ai[r]  = c * a0i - s * a1r;
        ar[pr] = c * a1r + s * a0i;
        ai[pr] = c * a1i - s * a0r;
    }
}

__device__ __forceinline__ void rz_shfl(float* ar, float* ai, float c, float s,
                                        unsigned lm)
{
#pragma unroll
    for (int r = 0; r < RPT; r++) {
        float br = __shfl_xor_sync(0xffffffffu, ar[r], lm);
        float bi = __shfl_xor_sync(0xffffffffu, ai[r], lm);
        float nr = c * ar[r] + s * bi;
        float ni = c * ai[r] - s * br;
        ar[r] = nr; ai[r] = ni;
    }
}

// ---- fan butterfly: new = 0.5*[(a+b) + D*(a-b)], D = tab[m+12] = (cos,sin) ----
__device__ __forceinline__ void fan_update(float& arr, float& aii, float br, float bi,
                                           const float2 t)
{
    float sr = arr + br, dr = arr - br;
    float si = aii + bi, di = aii - bi;
    float tr = t.x * dr + t.y * di;     // Re(D*d), D = cos - i*sin
    float ti = t.x * di - t.y * dr;     // Im(D*d)
    arr = 0.5f * (sr + tr);
    aii = 0.5f * (si + ti);
}

template<int TB>
__device__ __forceinline__ void fan_local(float* ar, float* ai, const float2* tab)
{
#pragma unroll
    for (int r = 0; r < RPT; r++) {
        if (r & (1 << TB)) continue;
        const int pr = r | (1 << TB);
        const int m = TB - 2 * __popc(r & ((1 << TB) - 1));
        const float2 t = tab[m + 12];
        float sr = ar[r] + ar[pr], dr = ar[r] - ar[pr];
        float si = ai[r] + ai[pr], di = ai[r] - ai[pr];
        float tr = t.x * dr + t.y * di;
        float ti = t.x * di - t.y * dr;
        ar[r]  = 0.5f * (sr + tr);  ai[r]  = 0.5f * (si + ti);
        ar[pr] = 0.5f * (sr - tr);  ai[pr] = 0.5f * (si - ti);
    }
}

// logical control bit cbit; partner via lane-bit mask lm; xbase = logical index
// of this thread's r=0 element.
__device__ __forceinline__ void fan_shfl(float* ar, float* ai, const float2* tab,
                                         int cbit, unsigned lm, int xbase)
{
#pragma unroll
    for (int r = 0; r < RPT; r++) {
        float br = __shfl_xor_sync(0xffffffffu, ar[r], lm);
        float bi = __shfl_xor_sync(0xffffffffu, ai[r], lm);
        const int x = xbase | r;
        const int m = cbit - 2 * __popc(x & ((1 << cbit) - 1));
        fan_update(ar[r], ai[r], br, bi, tab[m + 12]);
    }
}

// ---- H butterflies (unnormalized +/-) ----
template<int TB>
__device__ __forceinline__ void h_local(float* ar, float* ai)
{
#pragma unroll
    for (int r = 0; r < RPT; r++) {
        if (r & (1 << TB)) continue;
        const int pr = r | (1 << TB);
        float s0r = ar[r] + ar[pr], d0r = ar[r] - ar[pr];
        float s0i = ai[r] + ai[pr], d0i = ai[r] - ai[pr];
        ar[r] = s0r;  ai[r] = s0i;
        ar[pr] = d0r; ai[pr] = d0i;
    }
}

__device__ __forceinline__ void h_shfl(float* ar, float* ai, unsigned lm, int bitval)
{
    const float sg = bitval ? -1.f : 1.f;
#pragma unroll
    for (int r = 0; r < RPT; r++) {
        float br = __shfl_xor_sync(0xffffffffu, ar[r], lm);
        float bi = __shfl_xor_sync(0xffffffffu, ai[r], lm);
        ar[r] = br + sg * ar[r];
        ai[r] = bi + sg * ai[r];
    }
}

__global__ void __launch_bounds__(T1)
ansatz_kernel(const float* __restrict__ theta,
              const float* __restrict__ phi,
              const float* __restrict__ alpha)
{
    extern __shared__ float2 sh[];          // [0,DIM): staging; DIM..: tables
    float2* tab = sh + DIM;                 // 25 entries, idx m+12: (cos,sin)(ah*m)
    float2* rxt = sh + DIM + 32;            // 14 entries: (cos,sin)(th*(2p-13))
    const int tid  = threadIdx.x;
    const int lane = tid & 31;
    const int w    = tid >> 5;
    const int xb_n = tid << 3;              // normal-domain base index
    const int xb_t = (lane << 8) | (w << 3);// transposed-domain base index

    float ar[RPT], ai[RPT];
#pragma unroll
    for (int r = 0; r < RPT; r++) { ar[r] = 1.f; ai[r] = 0.f; }   // H^N|0> (unnorm)

    for (int l = 0; l < LAYERS; l++) {
        const float th  = 0.5f * theta[l];
        const float phh = 0.5f * phi[l];
        const float ah  = 0.5f * alpha[l];

        __syncthreads();                    // prior readers done before rewrite
        if (tid < 25) {
            float2 v; sincosf(ah * (float)(tid - 12), &v.y, &v.x);
            tab[tid] = v;
        } else if (tid >= 32 && tid < 32 + 14) {
            int p = tid - 32;
            float2 v; sincosf(th * (float)(2 * p - NQ), &v.y, &v.x);
            rxt[p] = v;
        }
        float cz, sz;
        sincosf(phh, &sz, &cz);
        __syncthreads();

        // Rx^N -> diagonal phase by popcount (domain-independent)
#pragma unroll
        for (int r = 0; r < RPT; r++) {
            const int p = __popc(xb_n | r);
            const float2 t = rxt[p];
            float nr = ar[r] * t.x - ai[r] * t.y;
            float ni = ar[r] * t.y + ai[r] * t.x;
            ar[r] = nr; ai[r] = ni;
        }

        // Rz^N: bits 0..2 local, 3..7 lane shuffles (normal domain)
        rz_local<0>(ar, ai, cz, sz);
        rz_local<1>(ar, ai, cz, sz);
        rz_local<2>(ar, ai, cz, sz);
#pragma unroll
        for (int tb = 3; tb <= 7; tb++) rz_shfl(ar, ai, cz, sz, 1u << (tb - 3));

        // ---- transposed domain: bits 8..12 live on lane bits ----
        transpose_wl(sh, ar, ai, w, lane);
#pragma unroll
        for (int tb = 8; tb <= 12; tb++) rz_shfl(ar, ai, cz, sz, 1u << (tb - 8));
#pragma unroll
        for (int c = 12; c >= 8; c--)
            fan_shfl(ar, ai, tab, c, 1u << (c - 8), xb_t);
        transpose_wl(sh, ar, ai, w, lane);
        // ---- back to normal domain ----

#pragma unroll
        for (int c = 7; c >= 3; c--)
            fan_shfl(ar, ai, tab, c, 1u << (c - 3), xb_n);
        fan_local<2>(ar, ai, tab);
        fan_local<1>(ar, ai, tab);
    }

    // back to computational basis: H^N (unnormalized; all H's commute)
    h_local<0>(ar, ai);
    h_local<1>(ar, ai);
    h_local<2>(ar, ai);
#pragma unroll
    for (int tb = 3; tb <= 7; tb++)
        h_shfl(ar, ai, 1u << (tb - 3), (tid >> (tb - 3)) & 1);
    transpose_wl(sh, ar, ai, w, lane);     // bits 8..12 -> lane bits
#pragma unroll
    for (int tb = 8; tb <= 12; tb++)
        h_shfl(ar, ai, 1u << (tb - 8), (lane >> (tb - 8)) & 1);

    // write psi with permuted index (state left in transposed domain)
    const float scale = 1.0f / 8192.0f;    // init 2^-6.5 * H^N 2^-6.5
    float z = 0.f;
#pragma unroll
    for (int r = 0; r < RPT; r++) {
        const int x = xb_t | r;
        float vr = ar[r] * scale, vi = ai[r] * scale;
        g_psi_re[x] = vr;
        g_psi_im[x] = vi;
        z += (vr * vr + vi * vi) * (float)(NQ - 2 * __popc(x));
    }

    __syncthreads();
    float* zs = (float*)sh;
#pragma unroll
    for (int o = 16; o > 0; o >>= 1) z += __shfl_xor_sync(0xffffffffu, z, o);
    if (lane == 0) zs[w] = z;
    __syncthreads();
    if (tid < 32) {
        float v = zs[tid];
#pragma unroll
        for (int o = 16; o > 0; o >>= 1) v += __shfl_xor_sync(0xffffffffu, v, o);
        if (tid == 0) g_z = v;
    }
}

// =========================================================================
// Bilinear kernel (unchanged): Re( conj(psi_r) * H_rc * psi_c ) partials
// =========================================================================
__global__ void __launch_bounds__(K2_THREADS)
bilinear_kernel(const float* __restrict__ Hr, const float* __restrict__ Hi)
{
    __shared__ float srr[ROWS_PER_BLK], sri[ROWS_PER_BLK];
    __shared__ float wsum[K2_THREADS / 32];

    const int t  = threadIdx.x;
    const int cg = blockIdx.x & (NCOL_GRPS - 1);
    const int rc = blockIdx.x >> 3;
    const int c0 = cg * COLS_PER_GRP + t * 4;
    const int r0 = rc * ROWS_PER_BLK;

    if (t < ROWS_PER_BLK) {
        srr[t] = g_psi_re[r0 + t];
        sri[t] = g_psi_im[r0 + t];
    }
    const float4 pcr = *(const float4*)(g_psi_re + c0);
    const float4 pci = *(const float4*)(g_psi_im + c0);
    __syncthreads();

    float acc = 0.f;
#pragma unroll 4
    for (int i = 0; i < ROWS_PER_BLK; i++) {
        const size_t off = (size_t)(r0 + i) * DIM + c0;
        const float4 hr = *(const float4*)(Hr + off);
        const float4 hi = *(const float4*)(Hi + off);
        const float prr = srr[i], pri = sri[i];

        float drr = 0.f, dri = 0.f;
        drr = fmaf(hr.x, pcr.x, drr); drr = fmaf(-hi.x, pci.x, drr);
        dri = fmaf(hr.x, pci.x, dri); dri = fmaf( hi.x, pcr.x, dri);
        drr = fmaf(hr.y, pcr.y, drr); drr = fmaf(-hi.y, pci.y, drr);
        dri = fmaf(hr.y, pci.y, dri); dri = fmaf( hi.y, pcr.y, dri);
        drr = fmaf(hr.z, pcr.z, drr); drr = fmaf(-hi.z, pci.z, drr);
        dri = fmaf(hr.z, pci.z, dri); dri = fmaf( hi.z, pcr.z, dri);
        drr = fmaf(hr.w, pcr.w, drr); drr = fmaf(-hi.w, pci.w, drr);
        dri = fmaf(hr.w, pci.w, dri); dri = fmaf( hi.w, pcr.w, dri);

        acc = fmaf(prr, drr, acc);
        acc = fmaf(pri, dri, acc);
    }

#pragma unroll
    for (int o = 16; o > 0; o >>= 1) acc += __shfl_xor_sync(0xffffffffu, acc, o);
    if ((t & 31) == 0) wsum[t >> 5] = acc;
    __syncthreads();
    if (t == 0) {
        float s = 0.f;
#pragma unroll
        for (int wi = 0; wi < K2_THREADS / 32; wi++) s += wsum[wi];
        g_partials[blockIdx.x] = s;
    }
}

// =========================================================================
__global__ void __launch_bounds__(256)
reduce_kernel(float* __restrict__ out, int out_size)
{
    __shared__ double wsumd[8];
    __shared__ float  res;
    const int t = threadIdx.x;

    double s = 0.0;
    for (int i = t; i < NBLK2; i += 256) s += (double)g_partials[i];
#pragma unroll
    for (int o = 16; o > 0; o >>= 1) s += __shfl_xor_sync(0xffffffffu, s, o);
    if ((t & 31) == 0) wsumd[t >> 5] = s;
    __syncthreads();
    if (t == 0) {
        double tot = 0.0;
#pragma unroll
        for (int wi = 0; wi < 8; wi++) tot += wsumd[wi];
        res = (float)(tot - 0.1 * (double)g_z);
    }
    __syncthreads();
    for (int i = t; i < out_size; i += 256) out[i] = res;
}

// =========================================================================
extern "C" void kernel_launch(void* const* d_in, const int* in_sizes, int n_in,
                              void* d_out, int out_size)
{
    const float* theta = (const float*)d_in[0];
    const float* phi   = (const float*)d_in[1];
    const float* alpha = (const float*)d_in[2];
    const float* Hr    = (const float*)d_in[3];
    const float* Hi    = (const float*)d_in[4];

    cudaFuncSetAttribute((const void*)ansatz_kernel,
                         cudaFuncAttributeMaxDynamicSharedMemorySize,
                         (DIM + 64) * sizeof(float2));

    ansatz_kernel<<<1, T1, (DIM + 64) * sizeof(float2)>>>(theta, phi, alpha);
    bilinear_kernel<<<NBLK2, K2_THREADS>>>(Hr, Hi);
    reduce_kernel<<<1, 256>>>((float*)d_out, out_size);
}